// round 8
// baseline (speedup 1.0000x reference)
#include <cuda_runtime.h>
#include <cuda_bf16.h>
#include <math.h>
#include <stdint.h>

// ---------------------------------------------------------------------------
// lstm_gcn round 8: int8 IMMA (m16n8k32) split-precision LSTM gate GEMM.
// x*16 = X1 + X2/256 ; h*64 = H1 + H2/256 ; Wih*1024 / Whh*256 = W1 + W2/256.
// acc = ((A1W2 + A2W1) + 128)>>8 + A1W1 ; gate = acc/16384 + bias. Exact int32
// accumulation; half the tensor instructions vs bf16 m16n8k16 (R4).
// ---------------------------------------------------------------------------

#define MAXN   50000
#define MAXSEQ 16
#define DIM    128
#define NG     512

__device__ float g_h[MAXN * DIM];
__device__ float g_c[MAXN * DIM];
__device__ float g_gates[MAXN * NG];
__device__ float g_t1[MAXN * DIM];
__device__ float g_t2[MAXN * DIM];
__device__ float g_bsum[NG];
__device__ int   g_eflag;

__device__ signed char g_x1[MAXSEQ * MAXN * DIM];
__device__ signed char g_x2[MAXSEQ * MAXN * DIM];
__device__ signed char g_h1[MAXN * DIM];
__device__ signed char g_h2[MAXN * DIM];
__device__ signed char g_w1[NG * 256];   // [512][256] = [Wih*1024 | Whh*256] hi
__device__ signed char g_w2[NG * 256];   // residual *256

// ------------------------------ helpers ------------------------------------
__device__ __forceinline__ uint32_t smem_u32(const void* p) {
    uint32_t a;
    asm("{ .reg .u64 t; cvta.to.shared.u64 t, %1; cvt.u32.u64 %0, t; }"
        : "=r"(a) : "l"(p));
    return a;
}

__device__ __forceinline__ void ldsm4(uint32_t* r, uint32_t addr) {
    asm volatile("ldmatrix.sync.aligned.m8n8.x4.shared.b16 {%0,%1,%2,%3}, [%4];"
                 : "=r"(r[0]), "=r"(r[1]), "=r"(r[2]), "=r"(r[3]) : "r"(addr));
}

__device__ __forceinline__ void mma_s8(int* d, const uint32_t* a,
                                       const uint32_t* b) {
    asm volatile(
        "mma.sync.aligned.m16n8k32.row.col.s32.s8.s8.s32 "
        "{%0,%1,%2,%3}, {%4,%5,%6,%7}, {%8,%9}, {%0,%1,%2,%3};"
        : "+r"(d[0]), "+r"(d[1]), "+r"(d[2]), "+r"(d[3])
        : "r"(a[0]), "r"(a[1]), "r"(a[2]), "r"(a[3]), "r"(b[0]), "r"(b[1]));
}

__device__ __forceinline__ void cp_async16(uint32_t dst, const void* src) {
    asm volatile("cp.async.cg.shared.global [%0], [%1], 16;"
                 :: "r"(dst), "l"(src));
}
__device__ __forceinline__ void cp_commit() {
    asm volatile("cp.async.commit_group;");
}
__device__ __forceinline__ void cp_wait1() {
    asm volatile("cp.async.wait_group 1;");
}
__device__ __forceinline__ void cp_wait0() {
    asm volatile("cp.async.wait_group 0;");
}

__device__ __forceinline__ signed char q8(float v) {
    int t = __float2int_rn(v);
    t = t > 127 ? 127 : (t < -127 ? -127 : t);
    return (signed char)t;
}

// ------------------------------ edge dtype detect --------------------------
__global__ void detect_edge_dtype_k(const int* __restrict__ e32, long long n32,
                                    int* __restrict__ flag) {
    __shared__ int nz;
    if (threadIdx.x == 0) nz = 0;
    __syncthreads();
    for (long long i = threadIdx.x; i < 4096; i += blockDim.x) {
        long long idx = 2 * i + 1;
        if (idx < n32 && e32[idx] != 0) atomicOr(&nz, 1);
    }
    __syncthreads();
    if (threadIdx.x == 0) *flag = (nz == 0) ? 1 : 0;
}

// ------------------------------ small kernels ------------------------------
__global__ void fill_zero_k(float* __restrict__ p, int n) {
    int i = blockIdx.x * blockDim.x + threadIdx.x;
    if (i < n) p[i] = 0.0f;
}

__global__ void bias_sum_k(const float* __restrict__ a, const float* __restrict__ b,
                           float* __restrict__ o) {
    int i = threadIdx.x;
    o[i] = a[i] + b[i];
}

__global__ void fill_bias_k(float* __restrict__ out, const float* __restrict__ b, int total) {
    int i = blockIdx.x * blockDim.x + threadIdx.x;
    if (i < total) out[i] = b[i & (DIM - 1)];
}

__global__ void relu_bias_k(const float* __restrict__ in, const float* __restrict__ b,
                            float* __restrict__ out, int total) {
    int i = blockIdx.x * blockDim.x + threadIdx.x;
    if (i < total) {
        float v = in[i] + b[i & (DIM - 1)];
        out[i] = v > 0.0f ? v : 0.0f;
    }
}

// quantize x: X1 = rn(x*16), X2 = rn((x*16 - X1)*256)
__global__ void quant_x_k(const float* __restrict__ src,
                          signed char* __restrict__ x1,
                          signed char* __restrict__ x2, int n4) {
    int i = blockIdx.x * blockDim.x + threadIdx.x;
    if (i >= n4) return;
    float4 v = ((const float4*)src)[i];
    char4 a1, a2;
    float q;
    q = v.x * 16.0f; a1.x = q8(q); a2.x = q8((q - (float)a1.x) * 256.0f);
    q = v.y * 16.0f; a1.y = q8(q); a2.y = q8((q - (float)a1.y) * 256.0f);
    q = v.z * 16.0f; a1.z = q8(q); a2.z = q8((q - (float)a1.z) * 256.0f);
    q = v.w * 16.0f; a1.w = q8(q); a2.w = q8((q - (float)a1.w) * 256.0f);
    ((char4*)x1)[i] = a1;
    ((char4*)x2)[i] = a2;
}

// quantize Wcat [512][256]: cols 0-127 Wih*1024, cols 128-255 Whh*256
__global__ void quant_w_k(const float* __restrict__ wih, const float* __restrict__ whh,
                          signed char* __restrict__ w1, signed char* __restrict__ w2) {
    int idx = blockIdx.x * blockDim.x + threadIdx.x;
    if (idx >= NG * 256) return;
    int n = idx >> 8, k = idx & 255;
    float w, sw;
    if (k < 128) { w = wih[n * 128 + k]; sw = 1024.0f; }
    else         { w = whh[n * 128 + (k - 128)]; sw = 256.0f; }
    float q = w * sw;
    signed char hi = q8(q);
    w1[idx] = hi;
    w2[idx] = q8((q - (float)hi) * 256.0f);
}

// ------------------------------ LSTM cell ----------------------------------
__device__ __forceinline__ float sigf(float x) {
    return 0.5f * (1.0f + tanhf(0.5f * x));
}

__global__ void lstm_cell_k(const float* __restrict__ gates,
                            float* __restrict__ c, float* __restrict__ h,
                            signed char* __restrict__ h1,
                            signed char* __restrict__ h2, int Nn) {
    int idx = blockIdx.x * blockDim.x + threadIdx.x;
    if (idx >= Nn * 32) return;
    int n = idx >> 5;
    int q = (idx & 31) * 4;
    const float* gr = gates + (size_t)n * NG + q;
    float4 gi = *(const float4*)(gr);
    float4 gf = *(const float4*)(gr + 128);
    float4 gg = *(const float4*)(gr + 256);
    float4 go = *(const float4*)(gr + 384);
    float* cp = c + (size_t)n * DIM + q;
    float* hp = h + (size_t)n * DIM + q;
    float4 cv = *(const float4*)cp;
    float4 cn, hn;
    cn.x = sigf(gf.x) * cv.x + sigf(gi.x) * tanhf(gg.x);
    cn.y = sigf(gf.y) * cv.y + sigf(gi.y) * tanhf(gg.y);
    cn.z = sigf(gf.z) * cv.z + sigf(gi.z) * tanhf(gg.z);
    cn.w = sigf(gf.w) * cv.w + sigf(gi.w) * tanhf(gg.w);
    hn.x = sigf(go.x) * tanhf(cn.x);
    hn.y = sigf(go.y) * tanhf(cn.y);
    hn.z = sigf(go.z) * tanhf(cn.z);
    hn.w = sigf(go.w) * tanhf(cn.w);
    *(float4*)cp = cn;
    *(float4*)hp = hn;
    char4 a1, a2;
    float t;
    t = hn.x * 64.0f; a1.x = q8(t); a2.x = q8((t - (float)a1.x) * 256.0f);
    t = hn.y * 64.0f; a1.y = q8(t); a2.y = q8((t - (float)a1.y) * 256.0f);
    t = hn.z * 64.0f; a1.z = q8(t); a2.z = q8((t - (float)a1.z) * 256.0f);
    t = hn.w * 64.0f; a1.w = q8(t); a2.w = q8((t - (float)a1.w) * 256.0f);
    *(char4*)(h1 + (size_t)n * DIM + q) = a1;
    *(char4*)(h2 + (size_t)n * DIM + q) = a2;
}

// ---------------------------------------------------------------------------
// LSTM gate GEMM via mma.sync int8 (m16n8k32).
// Block tile 128x128, 8 warps (2x4) of 64x32 warp tiles, BK=64 int8 (64B),
// double-buffered cp.async, 12 iterations:
//   iters 0-3: A1*W2 ; 4-7: A2*W1 ; then acc=(acc+128)>>8 ; 8-11: A1*W1.
// gate = acc/16384 + bias -> fp32 gates buffer.
// ---------------------------------------------------------------------------
#define ROWB 80     // 64B int8 data + 16B pad
#define ATILE 10240 // 128 * 80
#define NITER 12
#define INV_S 6.103515625e-05f   // 1/16384

__global__ __launch_bounds__(256, 2) void gemm_lstm_imma(
    const signed char* __restrict__ x1, const signed char* __restrict__ x2,
    const signed char* __restrict__ h1, const signed char* __restrict__ h2,
    const signed char* __restrict__ w1, const signed char* __restrict__ w2,
    const float* __restrict__ bias,
    float* __restrict__ C, int M) {
    __shared__ __align__(128) char sm[4 * ATILE];  // A0 A1 B0 B1

    int tid  = threadIdx.x;
    int wid  = tid >> 5;
    int lane = tid & 31;
    int m0 = blockIdx.x * 128;
    int n0 = blockIdx.y * 128;

    uint32_t sbase = smem_u32(sm);
    int wm = (wid >> 2) * 64;
    int wn = (wid & 3) * 32;

    int a_row  = (lane & 7) + ((lane >> 3) & 1) * 8;
    int a_kch  = lane >> 4;
    int b_row  = (lane & 7) + (lane >> 4) * 8;
    int b_kch  = (lane >> 3) & 1;

    int r0c = tid >> 2;
    int ch  = (tid & 3);

    int acc[4][4][4];
#pragma unroll
    for (int i = 0; i < 4; ++i)
#pragma unroll
        for (int j = 0; j < 4; ++j)
#pragma unroll
            for (int q = 0; q < 4; ++q) acc[i][j][q] = 0;

    auto issue = [&](int i, int b) {
        int pass = i >> 2;          // 0: A1*W2, 1: A2*W1, 2: A1*W1
        int kc   = i & 3;           // 0,1 -> x cols; 2,3 -> h cols
        bool xp  = kc < 2;
        const signed char* Ap = (pass == 1) ? (xp ? x2 : h2) : (xp ? x1 : h1);
        const signed char* Bp = (pass == 0) ? w2 : w1;
        int ka = (kc & 1) * 64;
        int kb = kc * 64;

        uint32_t dA = sbase + b * ATILE;
        uint32_t dB = sbase + 2 * ATILE + b * ATILE;
#pragma unroll
        for (int it = 0; it < 2; ++it) {
            int r = r0c + it * 64;
            int gm = m0 + r;
            const signed char* src =
                Ap + (size_t)(gm < M ? gm : 0) * DIM + ka + ch * 16;
            cp_async16(dA + r * ROWB + ch * 16, src);
        }
#pragma unroll
        for (int it = 0; it < 2; ++it) {
            int r = r0c + it * 64;
            const signed char* src = Bp + (size_t)(n0 + r) * 256 + kb + ch * 16;
            cp_async16(dB + r * ROWB + ch * 16, src);
        }
        cp_commit();
    };

    issue(0, 0);

    for (int i = 0; i < NITER; ++i) {
        if (i + 1 < NITER) issue(i + 1, (i + 1) & 1);
        if (i + 1 < NITER) cp_wait1(); else cp_wait0();
        __syncthreads();

        int b = i & 1;
        uint32_t sA = sbase + b * ATILE;
        uint32_t sB = sbase + 2 * ATILE + b * ATILE;

#pragma unroll
        for (int ks = 0; ks < 2; ++ks) {        // two k32 steps per iter
            uint32_t afr[4][4];
            uint32_t bfr[2][4];
#pragma unroll
            for (int fm = 0; fm < 4; ++fm) {
                uint32_t addr = sA + (wm + fm * 16 + a_row) * ROWB
                              + (ks * 2 + a_kch) * 16;
                ldsm4(afr[fm], addr);
            }
#pragma unroll
            for (int fn2 = 0; fn2 < 2; ++fn2) {
                uint32_t addr = sB + (wn + fn2 * 16 + b_row) * ROWB
                              + (ks * 2 + b_kch) * 16;
                ldsm4(bfr[fn2], addr);
            }
#pragma unroll
            for (int fm = 0; fm < 4; ++fm) {
#pragma unroll
                for (int fn = 0; fn < 4; ++fn)
                    mma_s8(acc[fm][fn], afr[fm], &bfr[fn >> 1][(fn & 1) * 2]);
            }
        }
        __syncthreads();

        if (i == 7) {   // corr passes done: acc <- (acc + 128) >> 8
#pragma unroll
            for (int fm = 0; fm < 4; ++fm)
#pragma unroll
                for (int fn = 0; fn < 4; ++fn)
#pragma unroll
                    for (int q = 0; q < 4; ++q)
                        acc[fm][fn][q] = (acc[fm][fn][q] + 128) >> 8;
        }
    }

    // ---- epilogue: scale, add bias, store fp32 gates ----
    int gid = lane >> 2;
    int tig = lane & 3;
    float2 bfr2[4];
#pragma unroll
    for (int fn = 0; fn < 4; ++fn) {
        int n = n0 + wn + fn * 8 + tig * 2;
        bfr2[fn] = *(const float2*)(bias + n);
    }
#pragma unroll
    for (int fm = 0; fm < 4; ++fm) {
        int mlo = m0 + wm + fm * 16 + gid;
        int mhi = mlo + 8;
#pragma unroll
        for (int fn = 0; fn < 4; ++fn) {
            int n = n0 + wn + fn * 8 + tig * 2;
            if (mlo < M) {
                float2 o = make_float2(
                    __int2float_rn(acc[fm][fn][0]) * INV_S + bfr2[fn].x,
                    __int2float_rn(acc[fm][fn][1]) * INV_S + bfr2[fn].y);
                *(float2*)(C + (size_t)mlo * NG + n) = o;
            }
            if (mhi < M) {
                float2 o = make_float2(
                    __int2float_rn(acc[fm][fn][2]) * INV_S + bfr2[fn].x,
                    __int2float_rn(acc[fm][fn][3]) * INV_S + bfr2[fn].y);
                *(float2*)(C + (size_t)mhi * NG + n) = o;
            }
        }
    }
}

// ------------------------------ GCN fp32 GEMM ------------------------------
#define BM 128
#define BN 128
#define BK 16
#define TM 8
#define TN 8

__global__ __launch_bounds__(256) void gemm_kn_k(
    const float* __restrict__ A, const float* __restrict__ B,
    float* __restrict__ C, int M) {
    __shared__ float As[BK][BM];
    __shared__ float Bs[BK][BN];
    int tid = threadIdx.x;
    int m0 = blockIdx.x * BM;
    int ty = tid >> 4;
    int tx = tid & 15;
    float acc[TM][TN] = {};

    for (int kc = 0; kc < 8; ++kc) {
        int kbase = kc * BK;
#pragma unroll
        for (int p = 0; p < 2; ++p) {
            int ar = (tid >> 2) + p * 64;
            int ac = (tid & 3) * 4;
            int gm = m0 + ar;
            float4 v = make_float4(0.f, 0.f, 0.f, 0.f);
            if (gm < M) v = *(const float4*)(A + (size_t)gm * DIM + kbase + ac);
            As[ac + 0][ar] = v.x; As[ac + 1][ar] = v.y;
            As[ac + 2][ar] = v.z; As[ac + 3][ar] = v.w;
        }
#pragma unroll
        for (int p = 0; p < 2; ++p) {
            int k = (tid >> 5) + p * 8;
            int c4 = (tid & 31) * 4;
            float4 v = *(const float4*)(B + (size_t)(kbase + k) * DIM + c4);
            *(float4*)&Bs[k][c4] = v;
        }
        __syncthreads();
#pragma unroll
        for (int k = 0; k < BK; ++k) {
            float a[TM], b[TN];
            *(float4*)&a[0] = *(const float4*)&As[k][ty * TM];
            *(float4*)&a[4] = *(const float4*)&As[k][ty * TM + 4];
            *(float4*)&b[0] = *(const float4*)&Bs[k][tx * TN];
            *(float4*)&b[4] = *(const float4*)&Bs[k][tx * TN + 4];
#pragma unroll
            for (int i = 0; i < TM; ++i)
#pragma unroll
                for (int j = 0; j < TN; ++j) acc[i][j] += a[i] * b[j];
        }
        __syncthreads();
    }

#pragma unroll
    for (int i = 0; i < TM; ++i) {
        int m = m0 + ty * TM + i;
        if (m >= M) continue;
        float* crow = C + (size_t)m * DIM + tx * TN;
#pragma unroll
        for (int j4 = 0; j4 < TN; j4 += 4) {
            float4 o;
            o.x = acc[i][j4 + 0]; o.y = acc[i][j4 + 1];
            o.z = acc[i][j4 + 2]; o.w = acc[i][j4 + 3];
            *(float4*)(crow + j4) = o;
        }
    }
}

// ------------------------------ GCN scatter --------------------------------
__global__ void scatter_add_k(const float* __restrict__ feat,
                              const void* __restrict__ edges_raw, long long E,
                              const int* __restrict__ eflag, int Nn,
                              float* __restrict__ out) {
    long long gt = (long long)blockIdx.x * blockDim.x + threadIdx.x;
    long long e = gt >> 5;
    if (e >= E) return;
    int lane = (int)(gt & 31);
    long long s, d;
    if (*eflag) {
        const long long* ed = (const long long*)edges_raw;
        s = ed[e];
        d = ed[E + e];
    } else {
        const int* ed = (const int*)edges_raw;
        s = ed[e];
        d = ed[E + e];
    }
    if (s < 0 || s >= Nn || d < 0 || d >= Nn) return;
    float4 v = *(const float4*)(feat + s * DIM + lane * 4);
    float* o = out + d * DIM + lane * 4;
    atomicAdd(o + 0, v.x);
    atomicAdd(o + 1, v.y);
    atomicAdd(o + 2, v.z);
    atomicAdd(o + 3, v.w);
}

// ------------------------------ host launcher ------------------------------
extern "C" void kernel_launch(void* const* d_in, const int* in_sizes, int n_in,
                              void* d_out, int out_size) {
    const float* input_aux = (const float*)d_in[0];
    const void*  edges     = d_in[1];
    const float* W_ih      = (const float*)d_in[2];
    const float* W_hh      = (const float*)d_in[3];
    const float* b_ih      = (const float*)d_in[4];
    const float* b_hh      = (const float*)d_in[5];
    const float* W1        = (const float*)d_in[6];
    const float* b1        = (const float*)d_in[7];
    const float* W2        = (const float*)d_in[8];
    const float* b2        = (const float*)d_in[9];
    float* out = (float*)d_out;

    int Nn  = out_size / DIM;
    int seq = in_sizes[0] / (Nn * DIM);
    long long E = (long long)in_sizes[1] / 2;

    float *h, *c, *gates, *t1, *t2, *bsum;
    int* eflag;
    signed char *x1, *x2, *h1, *h2, *w1q, *w2q;
    cudaGetSymbolAddress((void**)&h,     g_h);
    cudaGetSymbolAddress((void**)&c,     g_c);
    cudaGetSymbolAddress((void**)&gates, g_gates);
    cudaGetSymbolAddress((void**)&t1,    g_t1);
    cudaGetSymbolAddress((void**)&t2,    g_t2);
    cudaGetSymbolAddress((void**)&bsum,  g_bsum);
    cudaGetSymbolAddress((void**)&eflag, g_eflag);
    cudaGetSymbolAddress((void**)&x1,    g_x1);
    cudaGetSymbolAddress((void**)&x2,    g_x2);
    cudaGetSymbolAddress((void**)&h1,    g_h1);
    cudaGetSymbolAddress((void**)&h2,    g_h2);
    cudaGetSymbolAddress((void**)&w1q,   g_w1);
    cudaGetSymbolAddress((void**)&w2q,   g_w2);

    int nd = Nn * DIM;
    int eb = 256;

    detect_edge_dtype_k<<<1, 256>>>((const int*)edges, 2 * E, eflag);
    bias_sum_k<<<1, NG>>>(b_ih, b_hh, bsum);
    fill_zero_k<<<(nd + eb - 1) / eb, eb>>>(h, nd);
    fill_zero_k<<<(nd + eb - 1) / eb, eb>>>(c, nd);
    fill_zero_k<<<(nd / 4 + eb - 1) / eb, eb>>>((float*)h1, nd / 4);
    fill_zero_k<<<(nd / 4 + eb - 1) / eb, eb>>>((float*)h2, nd / 4);

    int xn4 = (seq * nd) / 4;
    quant_x_k<<<(xn4 + eb - 1) / eb, eb>>>(input_aux, x1, x2, xn4);
    quant_w_k<<<(NG * 256 + eb - 1) / eb, eb>>>(W_ih, W_hh, w1q, w2q);

    dim3 ggate((Nn + 127) / 128, 4);
    int cell_threads = Nn * 32;
    for (int t = 0; t < seq; ++t) {
        const signed char* xa = x1 + (size_t)t * nd;
        const signed char* xb = x2 + (size_t)t * nd;
        gemm_lstm_imma<<<ggate, 256>>>(xa, xb, h1, h2, w1q, w2q,
                                       bsum, gates, Nn);
        lstm_cell_k<<<(cell_threads + eb - 1) / eb, eb>>>(gates, c, h, h1, h2, Nn);
    }

    dim3 ggcn((Nn + BM - 1) / BM, 1);
    long long sth = E * 32;
    unsigned sblocks = (unsigned)((sth + eb - 1) / eb);

    gemm_kn_k<<<ggcn, 256>>>(h, W1, t1, Nn);
    fill_zero_k<<<(nd + eb - 1) / eb, eb>>>(t2, nd);
    scatter_add_k<<<sblocks, eb>>>(t1, edges, E, eflag, Nn, t2);
    relu_bias_k<<<(nd + eb - 1) / eb, eb>>>(t2, b1, t1, nd);

    gemm_kn_k<<<ggcn, 256>>>(t1, W2, t2, Nn);
    fill_bias_k<<<(nd + eb - 1) / eb, eb>>>(out, b2, nd);
    scatter_add_k<<<sblocks, eb>>>(t2, edges, E, eflag, Nn, out);
}

// round 9
// speedup vs baseline: 1.6267x; 1.6267x over previous
#include <cuda_runtime.h>
#include <cuda_bf16.h>
#include <cuda_fp16.h>
#include <math.h>
#include <stdint.h>

// ---------------------------------------------------------------------------
// lstm_gcn round 9: R4 bf16 mma.sync GEMM (best known) + fp16 gates buffer
// (halves gates round-trip), h fp32 stored only on final step.
// ---------------------------------------------------------------------------

#define MAXN   50000
#define MAXSEQ 16
#define DIM    128
#define NG     512

__device__ float  g_h[MAXN * DIM];
__device__ float  g_c[MAXN * DIM];
__device__ __half g_gates[MAXN * NG];
__device__ float  g_t1[MAXN * DIM];
__device__ float  g_t2[MAXN * DIM];
__device__ float  g_bsum[NG];
__device__ int    g_eflag;

__device__ __nv_bfloat16 g_xhi[MAXSEQ * MAXN * DIM];
__device__ __nv_bfloat16 g_xlo[MAXSEQ * MAXN * DIM];
__device__ __nv_bfloat16 g_hhi[MAXN * DIM];
__device__ __nv_bfloat16 g_hlo[MAXN * DIM];
__device__ __nv_bfloat16 g_wchi[NG * 256];   // [512][256] = [W_ih | W_hh] hi
__device__ __nv_bfloat16 g_wclo[NG * 256];   // lo

// ------------------------------ helpers ------------------------------------
__device__ __forceinline__ uint32_t smem_u32(const void* p) {
    uint32_t a;
    asm("{ .reg .u64 t; cvta.to.shared.u64 t, %1; cvt.u32.u64 %0, t; }"
        : "=r"(a) : "l"(p));
    return a;
}

__device__ __forceinline__ void ldsm4(uint32_t* r, uint32_t addr) {
    asm volatile("ldmatrix.sync.aligned.m8n8.x4.shared.b16 {%0,%1,%2,%3}, [%4];"
                 : "=r"(r[0]), "=r"(r[1]), "=r"(r[2]), "=r"(r[3]) : "r"(addr));
}

__device__ __forceinline__ void mma_bf16(float* d, const uint32_t* a,
                                         const uint32_t* b) {
    asm volatile(
        "mma.sync.aligned.m16n8k16.row.col.f32.bf16.bf16.f32 "
        "{%0,%1,%2,%3}, {%4,%5,%6,%7}, {%8,%9}, {%0,%1,%2,%3};"
        : "+f"(d[0]), "+f"(d[1]), "+f"(d[2]), "+f"(d[3])
        : "r"(a[0]), "r"(a[1]), "r"(a[2]), "r"(a[3]), "r"(b[0]), "r"(b[1]));
}

__device__ __forceinline__ void cp_async16(uint32_t dst, const void* src) {
    asm volatile("cp.async.cg.shared.global [%0], [%1], 16;"
                 :: "r"(dst), "l"(src));
}
__device__ __forceinline__ void cp_commit() {
    asm volatile("cp.async.commit_group;");
}
__device__ __forceinline__ void cp_wait1() {
    asm volatile("cp.async.wait_group 1;");
}
__device__ __forceinline__ void cp_wait0() {
    asm volatile("cp.async.wait_group 0;");
}

// ------------------------------ edge dtype detect --------------------------
__global__ void detect_edge_dtype_k(const int* __restrict__ e32, long long n32,
                                    int* __restrict__ flag) {
    __shared__ int nz;
    if (threadIdx.x == 0) nz = 0;
    __syncthreads();
    for (long long i = threadIdx.x; i < 4096; i += blockDim.x) {
        long long idx = 2 * i + 1;
        if (idx < n32 && e32[idx] != 0) atomicOr(&nz, 1);
    }
    __syncthreads();
    if (threadIdx.x == 0) *flag = (nz == 0) ? 1 : 0;
}

// ------------------------------ small kernels ------------------------------
__global__ void fill_zero_k(float* __restrict__ p, int n) {
    int i = blockIdx.x * blockDim.x + threadIdx.x;
    if (i < n) p[i] = 0.0f;
}

__global__ void bias_sum_k(const float* __restrict__ a, const float* __restrict__ b,
                           float* __restrict__ o) {
    int i = threadIdx.x;
    o[i] = a[i] + b[i];
}

__global__ void fill_bias_k(float* __restrict__ out, const float* __restrict__ b, int total) {
    int i = blockIdx.x * blockDim.x + threadIdx.x;
    if (i < total) out[i] = b[i & (DIM - 1)];
}

__global__ void relu_bias_k(const float* __restrict__ in, const float* __restrict__ b,
                            float* __restrict__ out, int total) {
    int i = blockIdx.x * blockDim.x + threadIdx.x;
    if (i < total) {
        float v = in[i] + b[i & (DIM - 1)];
        out[i] = v > 0.0f ? v : 0.0f;
    }
}

__global__ void split_bf16_k(const float* __restrict__ src,
                             __nv_bfloat16* __restrict__ hi,
                             __nv_bfloat16* __restrict__ lo, int n4) {
    int i = blockIdx.x * blockDim.x + threadIdx.x;
    if (i >= n4) return;
    float4 v = ((const float4*)src)[i];
    __nv_bfloat16 hx = __float2bfloat16(v.x), hy = __float2bfloat16(v.y);
    __nv_bfloat16 hz = __float2bfloat16(v.z), hw = __float2bfloat16(v.w);
    __nv_bfloat162* hp = (__nv_bfloat162*)(hi + (size_t)i * 4);
    __nv_bfloat162* lp = (__nv_bfloat162*)(lo + (size_t)i * 4);
    hp[0] = __nv_bfloat162(hx, hy);
    hp[1] = __nv_bfloat162(hz, hw);
    lp[0] = __nv_bfloat162(__float2bfloat16(v.x - __bfloat162float(hx)),
                           __float2bfloat16(v.y - __bfloat162float(hy)));
    lp[1] = __nv_bfloat162(__float2bfloat16(v.z - __bfloat162float(hz)),
                           __float2bfloat16(v.w - __bfloat162float(hw)));
}

__global__ void build_wcat_k(const float* __restrict__ wih, const float* __restrict__ whh,
                             __nv_bfloat16* __restrict__ hi, __nv_bfloat16* __restrict__ lo) {
    int idx = blockIdx.x * blockDim.x + threadIdx.x;
    if (idx >= NG * 256) return;
    int n = idx >> 8, k = idx & 255;
    float v = (k < 128) ? wih[n * 128 + k] : whh[n * 128 + (k - 128)];
    __nv_bfloat16 h = __float2bfloat16(v);
    hi[idx] = h;
    lo[idx] = __float2bfloat16(v - __bfloat162float(h));
}

// ------------------------------ LSTM cell ----------------------------------
__device__ __forceinline__ float sigf(float x) {
    return 0.5f * (1.0f + tanhf(0.5f * x));
}

__global__ void lstm_cell_k(const __half* __restrict__ gates,
                            float* __restrict__ c, float* __restrict__ h,
                            __nv_bfloat16* __restrict__ hhi,
                            __nv_bfloat16* __restrict__ hlo, int Nn,
                            int write_h) {
    int idx = blockIdx.x * blockDim.x + threadIdx.x;
    if (idx >= Nn * 32) return;
    int n = idx >> 5;
    int q = (idx & 31) * 4;
    const __half2* gr = (const __half2*)(gates + (size_t)n * NG + q);
    float2 i01 = __half22float2(gr[0]);
    float2 i23 = __half22float2(gr[1]);
    float2 f01 = __half22float2(gr[64]);   // +128 halves
    float2 f23 = __half22float2(gr[65]);
    float2 g01 = __half22float2(gr[128]);  // +256
    float2 g23 = __half22float2(gr[129]);
    float2 o01 = __half22float2(gr[192]);  // +384
    float2 o23 = __half22float2(gr[193]);
    float* cp = c + (size_t)n * DIM + q;
    float* hp = h + (size_t)n * DIM + q;
    float4 cv = *(const float4*)cp;
    float4 cn, hn;
    cn.x = sigf(f01.x) * cv.x + sigf(i01.x) * tanhf(g01.x);
    cn.y = sigf(f01.y) * cv.y + sigf(i01.y) * tanhf(g01.y);
    cn.z = sigf(f23.x) * cv.z + sigf(i23.x) * tanhf(g23.x);
    cn.w = sigf(f23.y) * cv.w + sigf(i23.y) * tanhf(g23.y);
    hn.x = sigf(o01.x) * tanhf(cn.x);
    hn.y = sigf(o01.y) * tanhf(cn.y);
    hn.z = sigf(o23.x) * tanhf(cn.z);
    hn.w = sigf(o23.y) * tanhf(cn.w);
    *(float4*)cp = cn;
    if (write_h) *(float4*)hp = hn;
    __nv_bfloat16 hx = __float2bfloat16(hn.x), hy = __float2bfloat16(hn.y);
    __nv_bfloat16 hz = __float2bfloat16(hn.z), hw = __float2bfloat16(hn.w);
    __nv_bfloat162* hip = (__nv_bfloat162*)(hhi + (size_t)n * DIM + q);
    __nv_bfloat162* lop = (__nv_bfloat162*)(hlo + (size_t)n * DIM + q);
    hip[0] = __nv_bfloat162(hx, hy);
    hip[1] = __nv_bfloat162(hz, hw);
    lop[0] = __nv_bfloat162(__float2bfloat16(hn.x - __bfloat162float(hx)),
                            __float2bfloat16(hn.y - __bfloat162float(hy)));
    lop[1] = __nv_bfloat162(__float2bfloat16(hn.z - __bfloat162float(hz)),
                            __float2bfloat16(hn.w - __bfloat162float(hw)));
}

// ---------------------------------------------------------------------------
// LSTM gate GEMM via mma.sync bf16 (R4 mainloop, fp16 gates epilogue).
// Block tile 128x128, 8 warps (2x4) of 64x32 warp tiles, BK=32, double-
// buffered cp.async. K loop: 3 passes x 256 (x | h), 24 iterations.
// ---------------------------------------------------------------------------
#define ROWB 80     // bytes per smem row (32 bf16 data + pad)
#define ATILE 10240 // 128 * 80
#define NITER 24

__global__ __launch_bounds__(256, 2) void gemm_lstm_mma(
    const __nv_bfloat16* __restrict__ xhi, const __nv_bfloat16* __restrict__ xlo,
    const __nv_bfloat16* __restrict__ hhi, const __nv_bfloat16* __restrict__ hlo,
    const __nv_bfloat16* __restrict__ whi, const __nv_bfloat16* __restrict__ wlo,
    const float* __restrict__ bias,
    __half* __restrict__ C, int M) {
    __shared__ __align__(128) char sm[4 * ATILE];  // A0 A1 B0 B1

    int tid  = threadIdx.x;
    int wid  = tid >> 5;
    int lane = tid & 31;
    int m0 = blockIdx.x * 128;
    int n0 = blockIdx.y * 128;

    uint32_t sbase = smem_u32(sm);
    int wm = (wid >> 2) * 64;
    int wn = (wid & 3) * 32;

    int a_row  = (lane & 7) + ((lane >> 3) & 1) * 8;
    int a_kch  = lane >> 4;
    int b_row  = (lane & 7) + (lane >> 4) * 8;
    int b_kch  = (lane >> 3) & 1;

    int r0c = tid >> 2;
    int ch  = (tid & 3);

    float acc[4][4][4];
#pragma unroll
    for (int i = 0; i < 4; ++i)
#pragma unroll
        for (int j = 0; j < 4; ++j)
#pragma unroll
            for (int q = 0; q < 4; ++q) acc[i][j][q] = 0.0f;

    auto issue = [&](int i, int b) {
        int pass = i >> 3;          // 0,1,2
        int kc   = i & 7;           // 0..7 over K=256
        bool xp  = kc < 4;
        const __nv_bfloat16* Ap = (pass == 2) ? (xp ? xlo : hlo)
                                              : (xp ? xhi : hhi);
        const __nv_bfloat16* Bp = (pass == 1) ? wlo : whi;
        int ka = (kc & 3) * 32;
        int kb = kc * 32;

        uint32_t dA = sbase + b * ATILE;
        uint32_t dB = sbase + 2 * ATILE + b * ATILE;
#pragma unroll
        for (int it = 0; it < 2; ++it) {
            int r = r0c + it * 64;
            int gm = m0 + r;
            const __nv_bfloat16* src =
                Ap + (size_t)(gm < M ? gm : 0) * DIM + ka + ch * 8;
            cp_async16(dA + r * ROWB + ch * 16, src);
        }
#pragma unroll
        for (int it = 0; it < 2; ++it) {
            int r = r0c + it * 64;
            const __nv_bfloat16* src = Bp + (size_t)(n0 + r) * 256 + kb + ch * 8;
            cp_async16(dB + r * ROWB + ch * 16, src);
        }
        cp_commit();
    };

    issue(0, 0);

    for (int i = 0; i < NITER; ++i) {
        if (i + 1 < NITER) issue(i + 1, (i + 1) & 1);
        if (i + 1 < NITER) cp_wait1(); else cp_wait0();
        __syncthreads();

        int b = i & 1;
        uint32_t sA = sbase + b * ATILE;
        uint32_t sB = sbase + 2 * ATILE + b * ATILE;

#pragma unroll
        for (int k16 = 0; k16 < 2; ++k16) {
            uint32_t afr[4][4];
            uint32_t bfr[2][4];
#pragma unroll
            for (int fm = 0; fm < 4; ++fm) {
                uint32_t addr = sA + (wm + fm * 16 + a_row) * ROWB
                              + (k16 * 2 + a_kch) * 16;
                ldsm4(afr[fm], addr);
            }
#pragma unroll
            for (int fn2 = 0; fn2 < 2; ++fn2) {
                uint32_t addr = sB + (wn + fn2 * 16 + b_row) * ROWB
                              + (k16 * 2 + b_kch) * 16;
                ldsm4(bfr[fn2], addr);
            }
#pragma unroll
            for (int fm = 0; fm < 4; ++fm) {
#pragma unroll
                for (int fn = 0; fn < 4; ++fn)
                    mma_bf16(acc[fm][fn], afr[fm], &bfr[fn >> 1][(fn & 1) * 2]);
            }
        }
        __syncthreads();
    }

    // ---- epilogue: add bias, store fp16 gates ----
    int gid = lane >> 2;
    int tig = lane & 3;
    float2 bfr2[4];
#pragma unroll
    for (int fn = 0; fn < 4; ++fn) {
        int n = n0 + wn + fn * 8 + tig * 2;
        bfr2[fn] = *(const float2*)(bias + n);
    }
#pragma unroll
    for (int fm = 0; fm < 4; ++fm) {
        int mlo = m0 + wm + fm * 16 + gid;
        int mhi = mlo + 8;
#pragma unroll
        for (int fn = 0; fn < 4; ++fn) {
            int n = n0 + wn + fn * 8 + tig * 2;
            if (mlo < M) {
                __half2 o = __floats2half2_rn(acc[fm][fn][0] + bfr2[fn].x,
                                              acc[fm][fn][1] + bfr2[fn].y);
                *(__half2*)(C + (size_t)mlo * NG + n) = o;
            }
            if (mhi < M) {
                __half2 o = __floats2half2_rn(acc[fm][fn][2] + bfr2[fn].x,
                                              acc[fm][fn][3] + bfr2[fn].y);
                *(__half2*)(C + (size_t)mhi * NG + n) = o;
            }
        }
    }
}

// ------------------------------ GCN fp32 GEMM ------------------------------
#define BM 128
#define BN 128
#define BK 16
#define TM 8
#define TN 8

__global__ __launch_bounds__(256) void gemm_kn_k(
    const float* __restrict__ A, const float* __restrict__ B,
    float* __restrict__ C, int M) {
    __shared__ float As[BK][BM];
    __shared__ float Bs[BK][BN];
    int tid = threadIdx.x;
    int m0 = blockIdx.x * BM;
    int ty = tid >> 4;
    int tx = tid & 15;
    float acc[TM][TN] = {};

    for (int kc = 0; kc < 8; ++kc) {
        int kbase = kc * BK;
#pragma unroll
        for (int p = 0; p < 2; ++p) {
            int ar = (tid >> 2) + p * 64;
            int ac = (tid & 3) * 4;
            int gm = m0 + ar;
            float4 v = make_float4(0.f, 0.f, 0.f, 0.f);
            if (gm < M) v = *(const float4*)(A + (size_t)gm * DIM + kbase + ac);
            As[ac + 0][ar] = v.x; As[ac + 1][ar] = v.y;
            As[ac + 2][ar] = v.z; As[ac + 3][ar] = v.w;
        }
#pragma unroll
        for (int p = 0; p < 2; ++p) {
            int k = (tid >> 5) + p * 8;
            int c4 = (tid & 31) * 4;
            float4 v = *(const float4*)(B + (size_t)(kbase + k) * DIM + c4);
            *(float4*)&Bs[k][c4] = v;
        }
        __syncthreads();
#pragma unroll
        for (int k = 0; k < BK; ++k) {
            float a[TM], b[TN];
            *(float4*)&a[0] = *(const float4*)&As[k][ty * TM];
            *(float4*)&a[4] = *(const float4*)&As[k][ty * TM + 4];
            *(float4*)&b[0] = *(const float4*)&Bs[k][tx * TN];
            *(float4*)&b[4] = *(const float4*)&Bs[k][tx * TN + 4];
#pragma unroll
            for (int i = 0; i < TM; ++i)
#pragma unroll
                for (int j = 0; j < TN; ++j) acc[i][j] += a[i] * b[j];
        }
        __syncthreads();
    }

#pragma unroll
    for (int i = 0; i < TM; ++i) {
        int m = m0 + ty * TM + i;
        if (m >= M) continue;
        float* crow = C + (size_t)m * DIM + tx * TN;
#pragma unroll
        for (int j4 = 0; j4 < TN; j4 += 4) {
            float4 o;
            o.x = acc[i][j4 + 0]; o.y = acc[i][j4 + 1];
            o.z = acc[i][j4 + 2]; o.w = acc[i][j4 + 3];
            *(float4*)(crow + j4) = o;
        }
    }
}

// ------------------------------ GCN scatter --------------------------------
__global__ void scatter_add_k(const float* __restrict__ feat,
                              const void* __restrict__ edges_raw, long long E,
                              const int* __restrict__ eflag, int Nn,
                              float* __restrict__ out) {
    long long gt = (long long)blockIdx.x * blockDim.x + threadIdx.x;
    long long e = gt >> 5;
    if (e >= E) return;
    int lane = (int)(gt & 31);
    long long s, d;
    if (*eflag) {
        const long long* ed = (const long long*)edges_raw;
        s = ed[e];
        d = ed[E + e];
    } else {
        const int* ed = (const int*)edges_raw;
        s = ed[e];
        d = ed[E + e];
    }
    if (s < 0 || s >= Nn || d < 0 || d >= Nn) return;
    float4 v = *(const float4*)(feat + s * DIM + lane * 4);
    float* o = out + d * DIM + lane * 4;
    atomicAdd(o + 0, v.x);
    atomicAdd(o + 1, v.y);
    atomicAdd(o + 2, v.z);
    atomicAdd(o + 3, v.w);
}

// ------------------------------ host launcher ------------------------------
extern "C" void kernel_launch(void* const* d_in, const int* in_sizes, int n_in,
                              void* d_out, int out_size) {
    const float* input_aux = (const float*)d_in[0];
    const void*  edges     = d_in[1];
    const float* W_ih      = (const float*)d_in[2];
    const float* W_hh      = (const float*)d_in[3];
    const float* b_ih      = (const float*)d_in[4];
    const float* b_hh      = (const float*)d_in[5];
    const float* W1        = (const float*)d_in[6];
    const float* b1        = (const float*)d_in[7];
    const float* W2        = (const float*)d_in[8];
    const float* b2        = (const float*)d_in[9];
    float* out = (float*)d_out;

    int Nn  = out_size / DIM;
    int seq = in_sizes[0] / (Nn * DIM);
    long long E = (long long)in_sizes[1] / 2;

    float *h, *c, *t1, *t2, *bsum;
    __half* gates;
    int* eflag;
    __nv_bfloat16 *xhi, *xlo, *hhi, *hlo, *wchi, *wclo;
    cudaGetSymbolAddress((void**)&h,     g_h);
    cudaGetSymbolAddress((void**)&c,     g_c);
    cudaGetSymbolAddress((void**)&gates, g_gates);
    cudaGetSymbolAddress((void**)&t1,    g_t1);
    cudaGetSymbolAddress((void**)&t2,    g_t2);
    cudaGetSymbolAddress((void**)&bsum,  g_bsum);
    cudaGetSymbolAddress((void**)&eflag, g_eflag);
    cudaGetSymbolAddress((void**)&xhi,   g_xhi);
    cudaGetSymbolAddress((void**)&xlo,   g_xlo);
    cudaGetSymbolAddress((void**)&hhi,   g_hhi);
    cudaGetSymbolAddress((void**)&hlo,   g_hlo);
    cudaGetSymbolAddress((void**)&wchi,  g_wchi);
    cudaGetSymbolAddress((void**)&wclo,  g_wclo);

    int nd = Nn * DIM;
    int eb = 256;

    detect_edge_dtype_k<<<1, 256>>>((const int*)edges, 2 * E, eflag);
    bias_sum_k<<<1, NG>>>(b_ih, b_hh, bsum);
    fill_zero_k<<<(nd + eb - 1) / eb, eb>>>(c, nd);
    fill_zero_k<<<(nd / 2 + eb - 1) / eb, eb>>>((float*)hhi, nd / 2);
    fill_zero_k<<<(nd / 2 + eb - 1) / eb, eb>>>((float*)hlo, nd / 2);

    int xn4 = (seq * nd) / 4;
    split_bf16_k<<<(xn4 + eb - 1) / eb, eb>>>(input_aux, xhi, xlo, xn4);
    build_wcat_k<<<(NG * 256 + eb - 1) / eb, eb>>>(W_ih, W_hh, wchi, wclo);

    dim3 ggate((Nn + 127) / 128, 4);
    int cell_threads = Nn * 32;
    for (int t = 0; t < seq; ++t) {
        const __nv_bfloat16* xh = xhi + (size_t)t * nd;
        const __nv_bfloat16* xl = xlo + (size_t)t * nd;
        gemm_lstm_mma<<<ggate, 256>>>(xh, xl, hhi, hlo, wchi, wclo,
                                      bsum, gates, Nn);
        lstm_cell_k<<<(cell_threads + eb - 1) / eb, eb>>>(
            gates, c, h, hhi, hlo, Nn, (t == seq - 1) ? 1 : 0);
    }

    dim3 ggcn((Nn + BM - 1) / BM, 1);
    long long sth = E * 32;
    unsigned sblocks = (unsigned)((sth + eb - 1) / eb);

    gemm_kn_k<<<ggcn, 256>>>(h, W1, t1, Nn);
    fill_zero_k<<<(nd + eb - 1) / eb, eb>>>(t2, nd);
    scatter_add_k<<<sblocks, eb>>>(t1, edges, E, eflag, Nn, t2);
    relu_bias_k<<<(nd + eb - 1) / eb, eb>>>(t2, b1, t1, nd);

    gemm_kn_k<<<ggcn, 256>>>(t1, W2, t2, Nn);
    fill_bias_k<<<(nd + eb - 1) / eb, eb>>>(out, b2, nd);
    scatter_add_k<<<sblocks, eb>>>(t2, edges, E, eflag, Nn, out);
}

// round 10
// speedup vs baseline: 1.9206x; 1.1807x over previous
#include <cuda_runtime.h>
#include <cuda_bf16.h>
#include <cuda_fp16.h>
#include <math.h>
#include <stdint.h>

// ---------------------------------------------------------------------------
// lstm_gcn round 10: R9 base (bf16 mma.sync 3-pass GEMM + fp16 gates) plus
//  (1) tanh.approx.f32 (MUFU.TANH) in the LSTM cell  -> ~3-4x fewer MUFU ops
//  (2) red.global.add.v4.f32 in the GCN scatter      -> 4x fewer RED ops
// ---------------------------------------------------------------------------

#define MAXN   50000
#define MAXSEQ 16
#define DIM    128
#define NG     512

__device__ float  g_h[MAXN * DIM];
__device__ float  g_c[MAXN * DIM];
__device__ __half g_gates[MAXN * NG];
__device__ float  g_t1[MAXN * DIM];
__device__ float  g_t2[MAXN * DIM];
__device__ float  g_bsum[NG];
__device__ int    g_eflag;

__device__ __nv_bfloat16 g_xhi[MAXSEQ * MAXN * DIM];
__device__ __nv_bfloat16 g_xlo[MAXSEQ * MAXN * DIM];
__device__ __nv_bfloat16 g_hhi[MAXN * DIM];
__device__ __nv_bfloat16 g_hlo[MAXN * DIM];
__device__ __nv_bfloat16 g_wchi[NG * 256];   // [512][256] = [W_ih | W_hh] hi
__device__ __nv_bfloat16 g_wclo[NG * 256];   // lo

// ------------------------------ helpers ------------------------------------
__device__ __forceinline__ uint32_t smem_u32(const void* p) {
    uint32_t a;
    asm("{ .reg .u64 t; cvta.to.shared.u64 t, %1; cvt.u32.u64 %0, t; }"
        : "=r"(a) : "l"(p));
    return a;
}

__device__ __forceinline__ void ldsm4(uint32_t* r, uint32_t addr) {
    asm volatile("ldmatrix.sync.aligned.m8n8.x4.shared.b16 {%0,%1,%2,%3}, [%4];"
                 : "=r"(r[0]), "=r"(r[1]), "=r"(r[2]), "=r"(r[3]) : "r"(addr));
}

__device__ __forceinline__ void mma_bf16(float* d, const uint32_t* a,
                                         const uint32_t* b) {
    asm volatile(
        "mma.sync.aligned.m16n8k16.row.col.f32.bf16.bf16.f32 "
        "{%0,%1,%2,%3}, {%4,%5,%6,%7}, {%8,%9}, {%0,%1,%2,%3};"
        : "+f"(d[0]), "+f"(d[1]), "+f"(d[2]), "+f"(d[3])
        : "r"(a[0]), "r"(a[1]), "r"(a[2]), "r"(a[3]), "r"(b[0]), "r"(b[1]));
}

__device__ __forceinline__ void cp_async16(uint32_t dst, const void* src) {
    asm volatile("cp.async.cg.shared.global [%0], [%1], 16;"
                 :: "r"(dst), "l"(src));
}
__device__ __forceinline__ void cp_commit() {
    asm volatile("cp.async.commit_group;");
}
__device__ __forceinline__ void cp_wait1() {
    asm volatile("cp.async.wait_group 1;");
}
__device__ __forceinline__ void cp_wait0() {
    asm volatile("cp.async.wait_group 0;");
}

// HW tanh (MUFU.TANH), rel err ~2^-11
__device__ __forceinline__ float tanh_fast(float x) {
    float y;
    asm("tanh.approx.f32 %0, %1;" : "=f"(y) : "f"(x));
    return y;
}
__device__ __forceinline__ float sigf(float x) {
    return fmaf(tanh_fast(0.5f * x), 0.5f, 0.5f);
}

// vector reduction (sm_90+): 4 floats in one op
__device__ __forceinline__ void red_add_v4(float* addr, float4 v) {
    asm volatile("red.global.add.v4.f32 [%0], {%1, %2, %3, %4};"
                 :: "l"(addr), "f"(v.x), "f"(v.y), "f"(v.z), "f"(v.w)
                 : "memory");
}

// ------------------------------ edge dtype detect --------------------------
__global__ void detect_edge_dtype_k(const int* __restrict__ e32, long long n32,
                                    int* __restrict__ flag) {
    __shared__ int nz;
    if (threadIdx.x == 0) nz = 0;
    __syncthreads();
    for (long long i = threadIdx.x; i < 4096; i += blockDim.x) {
        long long idx = 2 * i + 1;
        if (idx < n32 && e32[idx] != 0) atomicOr(&nz, 1);
    }
    __syncthreads();
    if (threadIdx.x == 0) *flag = (nz == 0) ? 1 : 0;
}

// ------------------------------ small kernels ------------------------------
__global__ void fill_zero_k(float* __restrict__ p, int n) {
    int i = blockIdx.x * blockDim.x + threadIdx.x;
    if (i < n) p[i] = 0.0f;
}

__global__ void bias_sum_k(const float* __restrict__ a, const float* __restrict__ b,
                           float* __restrict__ o) {
    int i = threadIdx.x;
    o[i] = a[i] + b[i];
}

__global__ void fill_bias_k(float* __restrict__ out, const float* __restrict__ b, int total) {
    int i = blockIdx.x * blockDim.x + threadIdx.x;
    if (i < total) out[i] = b[i & (DIM - 1)];
}

__global__ void relu_bias_k(const float* __restrict__ in, const float* __restrict__ b,
                            float* __restrict__ out, int total) {
    int i = blockIdx.x * blockDim.x + threadIdx.x;
    if (i < total) {
        float v = in[i] + b[i & (DIM - 1)];
        out[i] = v > 0.0f ? v : 0.0f;
    }
}

__global__ void split_bf16_k(const float* __restrict__ src,
                             __nv_bfloat16* __restrict__ hi,
                             __nv_bfloat16* __restrict__ lo, int n4) {
    int i = blockIdx.x * blockDim.x + threadIdx.x;
    if (i >= n4) return;
    float4 v = ((const float4*)src)[i];
    __nv_bfloat16 hx = __float2bfloat16(v.x), hy = __float2bfloat16(v.y);
    __nv_bfloat16 hz = __float2bfloat16(v.z), hw = __float2bfloat16(v.w);
    __nv_bfloat162* hp = (__nv_bfloat162*)(hi + (size_t)i * 4);
    __nv_bfloat162* lp = (__nv_bfloat162*)(lo + (size_t)i * 4);
    hp[0] = __nv_bfloat162(hx, hy);
    hp[1] = __nv_bfloat162(hz, hw);
    lp[0] = __nv_bfloat162(__float2bfloat16(v.x - __bfloat162float(hx)),
                           __float2bfloat16(v.y - __bfloat162float(hy)));
    lp[1] = __nv_bfloat162(__float2bfloat16(v.z - __bfloat162float(hz)),
                           __float2bfloat16(v.w - __bfloat162float(hw)));
}

__global__ void build_wcat_k(const float* __restrict__ wih, const float* __restrict__ whh,
                             __nv_bfloat16* __restrict__ hi, __nv_bfloat16* __restrict__ lo) {
    int idx = blockIdx.x * blockDim.x + threadIdx.x;
    if (idx >= NG * 256) return;
    int n = idx >> 8, k = idx & 255;
    float v = (k < 128) ? wih[n * 128 + k] : whh[n * 128 + (k - 128)];
    __nv_bfloat16 h = __float2bfloat16(v);
    hi[idx] = h;
    lo[idx] = __float2bfloat16(v - __bfloat162float(h));
}

// ------------------------------ LSTM cell ----------------------------------
__global__ void lstm_cell_k(const __half* __restrict__ gates,
                            float* __restrict__ c, float* __restrict__ h,
                            __nv_bfloat16* __restrict__ hhi,
                            __nv_bfloat16* __restrict__ hlo, int Nn,
                            int write_h) {
    int idx = blockIdx.x * blockDim.x + threadIdx.x;
    if (idx >= Nn * 32) return;
    int n = idx >> 5;
    int q = (idx & 31) * 4;
    const __half2* gr = (const __half2*)(gates + (size_t)n * NG + q);
    float2 i01 = __half22float2(gr[0]);
    float2 i23 = __half22float2(gr[1]);
    float2 f01 = __half22float2(gr[64]);   // +128 halves
    float2 f23 = __half22float2(gr[65]);
    float2 g01 = __half22float2(gr[128]);  // +256
    float2 g23 = __half22float2(gr[129]);
    float2 o01 = __half22float2(gr[192]);  // +384
    float2 o23 = __half22float2(gr[193]);
    float* cp = c + (size_t)n * DIM + q;
    float* hp = h + (size_t)n * DIM + q;
    float4 cv = *(const float4*)cp;
    float4 cn, hn;
    cn.x = sigf(f01.x) * cv.x + sigf(i01.x) * tanh_fast(g01.x);
    cn.y = sigf(f01.y) * cv.y + sigf(i01.y) * tanh_fast(g01.y);
    cn.z = sigf(f23.x) * cv.z + sigf(i23.x) * tanh_fast(g23.x);
    cn.w = sigf(f23.y) * cv.w + sigf(i23.y) * tanh_fast(g23.y);
    hn.x = sigf(o01.x) * tanh_fast(cn.x);
    hn.y = sigf(o01.y) * tanh_fast(cn.y);
    hn.z = sigf(o23.x) * tanh_fast(cn.z);
    hn.w = sigf(o23.y) * tanh_fast(cn.w);
    *(float4*)cp = cn;
    if (write_h) *(float4*)hp = hn;
    __nv_bfloat16 hx = __float2bfloat16(hn.x), hy = __float2bfloat16(hn.y);
    __nv_bfloat16 hz = __float2bfloat16(hn.z), hw = __float2bfloat16(hn.w);
    __nv_bfloat162* hip = (__nv_bfloat162*)(hhi + (size_t)n * DIM + q);
    __nv_bfloat162* lop = (__nv_bfloat162*)(hlo + (size_t)n * DIM + q);
    hip[0] = __nv_bfloat162(hx, hy);
    hip[1] = __nv_bfloat162(hz, hw);
    lop[0] = __nv_bfloat162(__float2bfloat16(hn.x - __bfloat162float(hx)),
                            __float2bfloat16(hn.y - __bfloat162float(hy)));
    lop[1] = __nv_bfloat162(__float2bfloat16(hn.z - __bfloat162float(hz)),
                            __float2bfloat16(hn.w - __bfloat162float(hw)));
}

// ---------------------------------------------------------------------------
// LSTM gate GEMM via mma.sync bf16 (R4 mainloop, fp16 gates epilogue).
// Block tile 128x128, 8 warps (2x4) of 64x32 warp tiles, BK=32, double-
// buffered cp.async. K loop: 3 passes x 256 (x | h), 24 iterations.
// ---------------------------------------------------------------------------
#define ROWB 80     // bytes per smem row (32 bf16 data + pad)
#define ATILE 10240 // 128 * 80
#define NITER 24

__global__ __launch_bounds__(256, 2) void gemm_lstm_mma(
    const __nv_bfloat16* __restrict__ xhi, const __nv_bfloat16* __restrict__ xlo,
    const __nv_bfloat16* __restrict__ hhi, const __nv_bfloat16* __restrict__ hlo,
    const __nv_bfloat16* __restrict__ whi, const __nv_bfloat16* __restrict__ wlo,
    const float* __restrict__ bias,
    __half* __restrict__ C, int M) {
    __shared__ __align__(128) char sm[4 * ATILE];  // A0 A1 B0 B1

    int tid  = threadIdx.x;
    int wid  = tid >> 5;
    int lane = tid & 31;
    int m0 = blockIdx.x * 128;
    int n0 = blockIdx.y * 128;

    uint32_t sbase = smem_u32(sm);
    int wm = (wid >> 2) * 64;
    int wn = (wid & 3) * 32;

    int a_row  = (lane & 7) + ((lane >> 3) & 1) * 8;
    int a_kch  = lane >> 4;
    int b_row  = (lane & 7) + (lane >> 4) * 8;
    int b_kch  = (lane >> 3) & 1;

    int r0c = tid >> 2;
    int ch  = (tid & 3);

    float acc[4][4][4];
#pragma unroll
    for (int i = 0; i < 4; ++i)
#pragma unroll
        for (int j = 0; j < 4; ++j)
#pragma unroll
            for (int q = 0; q < 4; ++q) acc[i][j][q] = 0.0f;

    auto issue = [&](int i, int b) {
        int pass = i >> 3;          // 0,1,2
        int kc   = i & 7;           // 0..7 over K=256
        bool xp  = kc < 4;
        const __nv_bfloat16* Ap = (pass == 2) ? (xp ? xlo : hlo)
                                              : (xp ? xhi : hhi);
        const __nv_bfloat16* Bp = (pass == 1) ? wlo : whi;
        int ka = (kc & 3) * 32;
        int kb = kc * 32;

        uint32_t dA = sbase + b * ATILE;
        uint32_t dB = sbase + 2 * ATILE + b * ATILE;
#pragma unroll
        for (int it = 0; it < 2; ++it) {
            int r = r0c + it * 64;
            int gm = m0 + r;
            const __nv_bfloat16* src =
                Ap + (size_t)(gm < M ? gm : 0) * DIM + ka + ch * 8;
            cp_async16(dA + r * ROWB + ch * 16, src);
        }
#pragma unroll
        for (int it = 0; it < 2; ++it) {
            int r = r0c + it * 64;
            const __nv_bfloat16* src = Bp + (size_t)(n0 + r) * 256 + kb + ch * 8;
            cp_async16(dB + r * ROWB + ch * 16, src);
        }
        cp_commit();
    };

    issue(0, 0);

    for (int i = 0; i < NITER; ++i) {
        if (i + 1 < NITER) issue(i + 1, (i + 1) & 1);
        if (i + 1 < NITER) cp_wait1(); else cp_wait0();
        __syncthreads();

        int b = i & 1;
        uint32_t sA = sbase + b * ATILE;
        uint32_t sB = sbase + 2 * ATILE + b * ATILE;

#pragma unroll
        for (int k16 = 0; k16 < 2; ++k16) {
            uint32_t afr[4][4];
            uint32_t bfr[2][4];
#pragma unroll
            for (int fm = 0; fm < 4; ++fm) {
                uint32_t addr = sA + (wm + fm * 16 + a_row) * ROWB
                              + (k16 * 2 + a_kch) * 16;
                ldsm4(afr[fm], addr);
            }
#pragma unroll
            for (int fn2 = 0; fn2 < 2; ++fn2) {
                uint32_t addr = sB + (wn + fn2 * 16 + b_row) * ROWB
                              + (k16 * 2 + b_kch) * 16;
                ldsm4(bfr[fn2], addr);
            }
#pragma unroll
            for (int fm = 0; fm < 4; ++fm) {
#pragma unroll
                for (int fn = 0; fn < 4; ++fn)
                    mma_bf16(acc[fm][fn], afr[fm], &bfr[fn >> 1][(fn & 1) * 2]);
            }
        }
        __syncthreads();
    }

    // ---- epilogue: add bias, store fp16 gates ----
    int gid = lane >> 2;
    int tig = lane & 3;
    float2 bfr2[4];
#pragma unroll
    for (int fn = 0; fn < 4; ++fn) {
        int n = n0 + wn + fn * 8 + tig * 2;
        bfr2[fn] = *(const float2*)(bias + n);
    }
#pragma unroll
    for (int fm = 0; fm < 4; ++fm) {
        int mlo = m0 + wm + fm * 16 + gid;
        int mhi = mlo + 8;
#pragma unroll
        for (int fn = 0; fn < 4; ++fn) {
            int n = n0 + wn + fn * 8 + tig * 2;
            if (mlo < M) {
                __half2 o = __floats2half2_rn(acc[fm][fn][0] + bfr2[fn].x,
                                              acc[fm][fn][1] + bfr2[fn].y);
                *(__half2*)(C + (size_t)mlo * NG + n) = o;
            }
            if (mhi < M) {
                __half2 o = __floats2half2_rn(acc[fm][fn][2] + bfr2[fn].x,
                                              acc[fm][fn][3] + bfr2[fn].y);
                *(__half2*)(C + (size_t)mhi * NG + n) = o;
            }
        }
    }
}

// ------------------------------ GCN fp32 GEMM ------------------------------
#define BM 128
#define BN 128
#define BK 16
#define TM 8
#define TN 8

__global__ __launch_bounds__(256) void gemm_kn_k(
    const float* __restrict__ A, const float* __restrict__ B,
    float* __restrict__ C, int M) {
    __shared__ float As[BK][BM];
    __shared__ float Bs[BK][BN];
    int tid = threadIdx.x;
    int m0 = blockIdx.x * BM;
    int ty = tid >> 4;
    int tx = tid & 15;
    float acc[TM][TN] = {};

    for (int kc = 0; kc < 8; ++kc) {
        int kbase = kc * BK;
#pragma unroll
        for (int p = 0; p < 2; ++p) {
            int ar = (tid >> 2) + p * 64;
            int ac = (tid & 3) * 4;
            int gm = m0 + ar;
            float4 v = make_float4(0.f, 0.f, 0.f, 0.f);
            if (gm < M) v = *(const float4*)(A + (size_t)gm * DIM + kbase + ac);
            As[ac + 0][ar] = v.x; As[ac + 1][ar] = v.y;
            As[ac + 2][ar] = v.z; As[ac + 3][ar] = v.w;
        }
#pragma unroll
        for (int p = 0; p < 2; ++p) {
            int k = (tid >> 5) + p * 8;
            int c4 = (tid & 31) * 4;
            float4 v = *(const float4*)(B + (size_t)(kbase + k) * DIM + c4);
            *(float4*)&Bs[k][c4] = v;
        }
        __syncthreads();
#pragma unroll
        for (int k = 0; k < BK; ++k) {
            float a[TM], b[TN];
            *(float4*)&a[0] = *(const float4*)&As[k][ty * TM];
            *(float4*)&a[4] = *(const float4*)&As[k][ty * TM + 4];
            *(float4*)&b[0] = *(const float4*)&Bs[k][tx * TN];
            *(float4*)&b[4] = *(const float4*)&Bs[k][tx * TN + 4];
#pragma unroll
            for (int i = 0; i < TM; ++i)
#pragma unroll
                for (int j = 0; j < TN; ++j) acc[i][j] += a[i] * b[j];
        }
        __syncthreads();
    }

#pragma unroll
    for (int i = 0; i < TM; ++i) {
        int m = m0 + ty * TM + i;
        if (m >= M) continue;
        float* crow = C + (size_t)m * DIM + tx * TN;
#pragma unroll
        for (int j4 = 0; j4 < TN; j4 += 4) {
            float4 o;
            o.x = acc[i][j4 + 0]; o.y = acc[i][j4 + 1];
            o.z = acc[i][j4 + 2]; o.w = acc[i][j4 + 3];
            *(float4*)(crow + j4) = o;
        }
    }
}

// ------------------------------ GCN scatter (vector RED) -------------------
__global__ void scatter_add_k(const float* __restrict__ feat,
                              const void* __restrict__ edges_raw, long long E,
                              const int* __restrict__ eflag, int Nn,
                              float* __restrict__ out) {
    long long gt = (long long)blockIdx.x * blockDim.x + threadIdx.x;
    long long e = gt >> 5;
    if (e >= E) return;
    int lane = (int)(gt & 31);
    long long s, d;
    if (*eflag) {
        const long long* ed = (const long long*)edges_raw;
        s = ed[e];
        d = ed[E + e];
    } else {
        const int* ed = (const int*)edges_raw;
        s = ed[e];
        d = ed[E + e];
    }
    if (s < 0 || s >= Nn || d < 0 || d >= Nn) return;
    float4 v = *(const float4*)(feat + s * DIM + lane * 4);
    red_add_v4(out + d * DIM + lane * 4, v);
}

// ------------------------------ host launcher ------------------------------
extern "C" void kernel_launch(void* const* d_in, const int* in_sizes, int n_in,
                              void* d_out, int out_size) {
    const float* input_aux = (const float*)d_in[0];
    const void*  edges     = d_in[1];
    const float* W_ih      = (const float*)d_in[2];
    const float* W_hh      = (const float*)d_in[3];
    const float* b_ih      = (const float*)d_in[4];
    const float* b_hh      = (const float*)d_in[5];
    const float* W1        = (const float*)d_in[6];
    const float* b1        = (const float*)d_in[7];
    const float* W2        = (const float*)d_in[8];
    const float* b2        = (const float*)d_in[9];
    float* out = (float*)d_out;

    int Nn  = out_size / DIM;
    int seq = in_sizes[0] / (Nn * DIM);
    long long E = (long long)in_sizes[1] / 2;

    float *h, *c, *t1, *t2, *bsum;
    __half* gates;
    int* eflag;
    __nv_bfloat16 *xhi, *xlo, *hhi, *hlo, *wchi, *wclo;
    cudaGetSymbolAddress((void**)&h,     g_h);
    cudaGetSymbolAddress((void**)&c,     g_c);
    cudaGetSymbolAddress((void**)&gates, g_gates);
    cudaGetSymbolAddress((void**)&t1,    g_t1);
    cudaGetSymbolAddress((void**)&t2,    g_t2);
    cudaGetSymbolAddress((void**)&bsum,  g_bsum);
    cudaGetSymbolAddress((void**)&eflag, g_eflag);
    cudaGetSymbolAddress((void**)&xhi,   g_xhi);
    cudaGetSymbolAddress((void**)&xlo,   g_xlo);
    cudaGetSymbolAddress((void**)&hhi,   g_hhi);
    cudaGetSymbolAddress((void**)&hlo,   g_hlo);
    cudaGetSymbolAddress((void**)&wchi,  g_wchi);
    cudaGetSymbolAddress((void**)&wclo,  g_wclo);

    int nd = Nn * DIM;
    int eb = 256;

    detect_edge_dtype_k<<<1, 256>>>((const int*)edges, 2 * E, eflag);
    bias_sum_k<<<1, NG>>>(b_ih, b_hh, bsum);
    fill_zero_k<<<(nd + eb - 1) / eb, eb>>>(c, nd);
    fill_zero_k<<<(nd / 2 + eb - 1) / eb, eb>>>((float*)hhi, nd / 2);
    fill_zero_k<<<(nd / 2 + eb - 1) / eb, eb>>>((float*)hlo, nd / 2);

    int xn4 = (seq * nd) / 4;
    split_bf16_k<<<(xn4 + eb - 1) / eb, eb>>>(input_aux, xhi, xlo, xn4);
    build_wcat_k<<<(NG * 256 + eb - 1) / eb, eb>>>(W_ih, W_hh, wchi, wclo);

    dim3 ggate((Nn + 127) / 128, 4);
    int cell_threads = Nn * 32;
    for (int t = 0; t < seq; ++t) {
        const __nv_bfloat16* xh = xhi + (size_t)t * nd;
        const __nv_bfloat16* xl = xlo + (size_t)t * nd;
        gemm_lstm_mma<<<ggate, 256>>>(xh, xl, hhi, hlo, wchi, wclo,
                                      bsum, gates, Nn);
        lstm_cell_k<<<(cell_threads + eb - 1) / eb, eb>>>(
            gates, c, h, hhi, hlo, Nn, (t == seq - 1) ? 1 : 0);
    }

    dim3 ggcn((Nn + BM - 1) / BM, 1);
    long long sth = E * 32;
    unsigned sblocks = (unsigned)((sth + eb - 1) / eb);

    gemm_kn_k<<<ggcn, 256>>>(h, W1, t1, Nn);
    fill_zero_k<<<(nd + eb - 1) / eb, eb>>>(t2, nd);
    scatter_add_k<<<sblocks, eb>>>(t1, edges, E, eflag, Nn, t2);
    relu_bias_k<<<(nd + eb - 1) / eb, eb>>>(t2, b1, t1, nd);

    gemm_kn_k<<<ggcn, 256>>>(t1, W2, t2, Nn);
    fill_bias_k<<<(nd + eb - 1) / eb, eb>>>(out, b2, nd);
    scatter_add_k<<<sblocks, eb>>>(t2, edges, E, eflag, Nn, out);
}

// round 12
// speedup vs baseline: 3.5754x; 1.8616x over previous
#include <cuda_runtime.h>
#include <cuda_bf16.h>
#include <cuda_fp16.h>
#include <math.h>
#include <stdint.h>

// ---------------------------------------------------------------------------
// lstm_gcn round 12: SINGLE-PASS fp16 mma.sync LSTM gate GEMM (3x fewer
// tensor ops than the 3-pass bf16 split; justified by measured error
// attenuation: fp16 gate storage error ~2.4e-4 -> final rel_err 2e-5).
// Keeps R10's MUFU.TANH cell + red.v4 scatter. (R11 resubmit, typo fixed.)
// ---------------------------------------------------------------------------

#define MAXN   50000
#define MAXSEQ 16
#define DIM    128
#define NG     512

__device__ float  g_h[MAXN * DIM];
__device__ float  g_c[MAXN * DIM];
__device__ __half g_gates[MAXN * NG];
__device__ float  g_t1[MAXN * DIM];
__device__ float  g_t2[MAXN * DIM];
__device__ float  g_bsum[NG];
__device__ int    g_eflag;

__device__ __half g_xh[MAXSEQ * MAXN * DIM];   // x in fp16
__device__ __half g_hh[MAXN * DIM];            // h in fp16
__device__ __half g_wc[NG * 256];              // [512][256] = [W_ih | W_hh] fp16

// ------------------------------ helpers ------------------------------------
__device__ __forceinline__ uint32_t smem_u32(const void* p) {
    uint32_t a;
    asm("{ .reg .u64 t; cvta.to.shared.u64 t, %1; cvt.u32.u64 %0, t; }"
        : "=r"(a) : "l"(p));
    return a;
}

__device__ __forceinline__ void ldsm4(uint32_t* r, uint32_t addr) {
    asm volatile("ldmatrix.sync.aligned.m8n8.x4.shared.b16 {%0,%1,%2,%3}, [%4];"
                 : "=r"(r[0]), "=r"(r[1]), "=r"(r[2]), "=r"(r[3]) : "r"(addr));
}

__device__ __forceinline__ void mma_f16(float* d, const uint32_t* a,
                                        const uint32_t* b) {
    asm volatile(
        "mma.sync.aligned.m16n8k16.row.col.f32.f16.f16.f32 "
        "{%0,%1,%2,%3}, {%4,%5,%6,%7}, {%8,%9}, {%0,%1,%2,%3};"
        : "+f"(d[0]), "+f"(d[1]), "+f"(d[2]), "+f"(d[3])
        : "r"(a[0]), "r"(a[1]), "r"(a[2]), "r"(a[3]), "r"(b[0]), "r"(b[1]));
}

__device__ __forceinline__ void cp_async16(uint32_t dst, const void* src) {
    asm volatile("cp.async.cg.shared.global [%0], [%1], 16;"
                 :: "r"(dst), "l"(src));
}
__device__ __forceinline__ void cp_commit() {
    asm volatile("cp.async.commit_group;");
}
__device__ __forceinline__ void cp_wait1() {
    asm volatile("cp.async.wait_group 1;");
}
__device__ __forceinline__ void cp_wait0() {
    asm volatile("cp.async.wait_group 0;");
}

// HW tanh (MUFU.TANH), rel err ~2^-11
__device__ __forceinline__ float tanh_fast(float x) {
    float y;
    asm("tanh.approx.f32 %0, %1;" : "=f"(y) : "f"(x));
    return y;
}
__device__ __forceinline__ float sigf(float x) {
    return fmaf(tanh_fast(0.5f * x), 0.5f, 0.5f);
}

// vector reduction (sm_90+): 4 floats in one op
__device__ __forceinline__ void red_add_v4(float* addr, float4 v) {
    asm volatile("red.global.add.v4.f32 [%0], {%1, %2, %3, %4};"
                 :: "l"(addr), "f"(v.x), "f"(v.y), "f"(v.z), "f"(v.w)
                 : "memory");
}

// ------------------------------ edge dtype detect --------------------------
__global__ void detect_edge_dtype_k(const int* __restrict__ e32, long long n32,
                                    int* __restrict__ flag) {
    __shared__ int nz;
    if (threadIdx.x == 0) nz = 0;
    __syncthreads();
    for (long long i = threadIdx.x; i < 4096; i += blockDim.x) {
        long long idx = 2 * i + 1;
        if (idx < n32 && e32[idx] != 0) atomicOr(&nz, 1);
    }
    __syncthreads();
    if (threadIdx.x == 0) *flag = (nz == 0) ? 1 : 0;
}

// ------------------------------ small kernels ------------------------------
__global__ void fill_zero_k(float* __restrict__ p, int n) {
    int i = blockIdx.x * blockDim.x + threadIdx.x;
    if (i < n) p[i] = 0.0f;
}

__global__ void bias_sum_k(const float* __restrict__ a, const float* __restrict__ b,
                           float* __restrict__ o) {
    int i = threadIdx.x;
    o[i] = a[i] + b[i];
}

__global__ void fill_bias_k(float* __restrict__ out, const float* __restrict__ b, int total) {
    int i = blockIdx.x * blockDim.x + threadIdx.x;
    if (i < total) out[i] = b[i & (DIM - 1)];
}

__global__ void relu_bias_k(const float* __restrict__ in, const float* __restrict__ b,
                            float* __restrict__ out, int total) {
    int i = blockIdx.x * blockDim.x + threadIdx.x;
    if (i < total) {
        float v = in[i] + b[i & (DIM - 1)];
        out[i] = v > 0.0f ? v : 0.0f;
    }
}

// fp32 -> fp16 convert (vectorized x4)
__global__ void cvt_half_k(const float* __restrict__ src,
                           __half* __restrict__ dst, int n4) {
    int i = blockIdx.x * blockDim.x + threadIdx.x;
    if (i >= n4) return;
    float4 v = ((const float4*)src)[i];
    __half2* dp = (__half2*)(dst + (size_t)i * 4);
    dp[0] = __floats2half2_rn(v.x, v.y);
    dp[1] = __floats2half2_rn(v.z, v.w);
}

// Wcat[512][256] = [W_ih | W_hh] in fp16
__global__ void build_wcat_k(const float* __restrict__ wih, const float* __restrict__ whh,
                             __half* __restrict__ wc) {
    int idx = blockIdx.x * blockDim.x + threadIdx.x;
    if (idx >= NG * 256) return;
    int n = idx >> 8, k = idx & 255;
    float v = (k < 128) ? wih[n * 128 + k] : whh[n * 128 + (k - 128)];
    wc[idx] = __float2half_rn(v);
}

// ------------------------------ LSTM cell ----------------------------------
__global__ void lstm_cell_k(const __half* __restrict__ gates,
                            float* __restrict__ c, float* __restrict__ h,
                            __half* __restrict__ hh, int Nn, int write_h) {
    int idx = blockIdx.x * blockDim.x + threadIdx.x;
    if (idx >= Nn * 32) return;
    int n = idx >> 5;
    int q = (idx & 31) * 4;
    const __half2* gr = (const __half2*)(gates + (size_t)n * NG + q);
    float2 i01 = __half22float2(gr[0]);
    float2 i23 = __half22float2(gr[1]);
    float2 f01 = __half22float2(gr[64]);   // +128 halves
    float2 f23 = __half22float2(gr[65]);
    float2 g01 = __half22float2(gr[128]);  // +256
    float2 g23 = __half22float2(gr[129]);
    float2 o01 = __half22float2(gr[192]);  // +384
    float2 o23 = __half22float2(gr[193]);
    float* cp = c + (size_t)n * DIM + q;
    float* hp = h + (size_t)n * DIM + q;
    float4 cv = *(const float4*)cp;
    float4 cn, hn;
    cn.x = sigf(f01.x) * cv.x + sigf(i01.x) * tanh_fast(g01.x);
    cn.y = sigf(f01.y) * cv.y + sigf(i01.y) * tanh_fast(g01.y);
    cn.z = sigf(f23.x) * cv.z + sigf(i23.x) * tanh_fast(g23.x);
    cn.w = sigf(f23.y) * cv.w + sigf(i23.y) * tanh_fast(g23.y);
    hn.x = sigf(o01.x) * tanh_fast(cn.x);
    hn.y = sigf(o01.y) * tanh_fast(cn.y);
    hn.z = sigf(o23.x) * tanh_fast(cn.z);
    hn.w = sigf(o23.y) * tanh_fast(cn.w);
    *(float4*)cp = cn;
    if (write_h) *(float4*)hp = hn;
    __half2* hhp = (__half2*)(hh + (size_t)n * DIM + q);
    hhp[0] = __floats2half2_rn(hn.x, hn.y);
    hhp[1] = __floats2half2_rn(hn.z, hn.w);
}

// ---------------------------------------------------------------------------
// LSTM gate GEMM via mma.sync fp16, SINGLE pass.
// Block tile 128x128, 8 warps (2x4) of 64x32 warp tiles, BK=32, double-
// buffered cp.async. K loop: 8 iterations over K=256 ([x | h]).
// ---------------------------------------------------------------------------
#define ROWB 80     // bytes per smem row (32 fp16 data + pad)
#define ATILE 10240 // 128 * 80
#define NITER 8

__global__ __launch_bounds__(256, 2) void gemm_lstm_mma(
    const __half* __restrict__ xh, const __half* __restrict__ hh,
    const __half* __restrict__ wc,
    const float* __restrict__ bias,
    __half* __restrict__ C, int M) {
    __shared__ __align__(128) char sm[4 * ATILE];  // A0 A1 B0 B1

    int tid  = threadIdx.x;
    int wid  = tid >> 5;
    int lane = tid & 31;
    int m0 = blockIdx.x * 128;
    int n0 = blockIdx.y * 128;

    uint32_t sbase = smem_u32(sm);
    int wm = (wid >> 2) * 64;
    int wn = (wid & 3) * 32;

    int a_row  = (lane & 7) + ((lane >> 3) & 1) * 8;
    int a_kch  = lane >> 4;
    int b_row  = (lane & 7) + (lane >> 4) * 8;
    int b_kch  = (lane >> 3) & 1;

    int r0c = tid >> 2;
    int ch  = (tid & 3);

    float acc[4][4][4];
#pragma unroll
    for (int i = 0; i < 4; ++i)
#pragma unroll
        for (int j = 0; j < 4; ++j)
#pragma unroll
            for (int q = 0; q < 4; ++q) acc[i][j][q] = 0.0f;

    auto issue = [&](int i, int b) {
        int kc = i & 7;             // 0..7 over K=256
        const __half* Ap = (kc < 4) ? xh : hh;
        int ka = (kc & 3) * 32;
        int kb = kc * 32;

        uint32_t dA = sbase + b * ATILE;
        uint32_t dB = sbase + 2 * ATILE + b * ATILE;
#pragma unroll
        for (int it = 0; it < 2; ++it) {
            int r = r0c + it * 64;
            int gm = m0 + r;
            const __half* src =
                Ap + (size_t)(gm < M ? gm : 0) * DIM + ka + ch * 8;
            cp_async16(dA + r * ROWB + ch * 16, src);
        }
#pragma unroll
        for (int it = 0; it < 2; ++it) {
            int r = r0c + it * 64;
            const __half* src = wc + (size_t)(n0 + r) * 256 + kb + ch * 8;
            cp_async16(dB + r * ROWB + ch * 16, src);
        }
        cp_commit();
    };

    issue(0, 0);

    for (int i = 0; i < NITER; ++i) {
        if (i + 1 < NITER) issue(i + 1, (i + 1) & 1);
        if (i + 1 < NITER) cp_wait1(); else cp_wait0();
        __syncthreads();

        int b = i & 1;
        uint32_t sA = sbase + b * ATILE;
        uint32_t sB = sbase + 2 * ATILE + b * ATILE;

#pragma unroll
        for (int k16 = 0; k16 < 2; ++k16) {
            uint32_t afr[4][4];
            uint32_t bfr[2][4];
#pragma unroll
            for (int fm = 0; fm < 4; ++fm) {
                uint32_t addr = sA + (wm + fm * 16 + a_row) * ROWB
                              + (k16 * 2 + a_kch) * 16;
                ldsm4(afr[fm], addr);
            }
#pragma unroll
            for (int fn2 = 0; fn2 < 2; ++fn2) {
                uint32_t addr = sB + (wn + fn2 * 16 + b_row) * ROWB
                              + (k16 * 2 + b_kch) * 16;
                ldsm4(bfr[fn2], addr);
            }
#pragma unroll
            for (int fm = 0; fm < 4; ++fm) {
#pragma unroll
                for (int fn = 0; fn < 4; ++fn)
                    mma_f16(acc[fm][fn], afr[fm], &bfr[fn >> 1][(fn & 1) * 2]);
            }
        }
        __syncthreads();
    }

    // ---- epilogue: add bias, store fp16 gates ----
    int gid = lane >> 2;
    int tig = lane & 3;
    float2 bfr2[4];
#pragma unroll
    for (int fn = 0; fn < 4; ++fn) {
        int n = n0 + wn + fn * 8 + tig * 2;
        bfr2[fn] = *(const float2*)(bias + n);
    }
#pragma unroll
    for (int fm = 0; fm < 4; ++fm) {
        int mlo = m0 + wm + fm * 16 + gid;
        int mhi = mlo + 8;
#pragma unroll
        for (int fn = 0; fn < 4; ++fn) {
            int n = n0 + wn + fn * 8 + tig * 2;
            if (mlo < M) {
                __half2 o = __floats2half2_rn(acc[fm][fn][0] + bfr2[fn].x,
                                              acc[fm][fn][1] + bfr2[fn].y);
                *(__half2*)(C + (size_t)mlo * NG + n) = o;
            }
            if (mhi < M) {
                __half2 o = __floats2half2_rn(acc[fm][fn][2] + bfr2[fn].x,
                                              acc[fm][fn][3] + bfr2[fn].y);
                *(__half2*)(C + (size_t)mhi * NG + n) = o;
            }
        }
    }
}

// ------------------------------ GCN fp32 GEMM ------------------------------
#define BM 128
#define BN 128
#define BK 16
#define TM 8
#define TN 8

__global__ __launch_bounds__(256) void gemm_kn_k(
    const float* __restrict__ A, const float* __restrict__ B,
    float* __restrict__ C, int M) {
    __shared__ float As[BK][BM];
    __shared__ float Bs[BK][BN];
    int tid = threadIdx.x;
    int m0 = blockIdx.x * BM;
    int ty = tid >> 4;
    int tx = tid & 15;
    float acc[TM][TN] = {};

    for (int kc = 0; kc < 8; ++kc) {
        int kbase = kc * BK;
#pragma unroll
        for (int p = 0; p < 2; ++p) {
            int ar = (tid >> 2) + p * 64;
            int ac = (tid & 3) * 4;
            int gm = m0 + ar;
            float4 v = make_float4(0.f, 0.f, 0.f, 0.f);
            if (gm < M) v = *(const float4*)(A + (size_t)gm * DIM + kbase + ac);
            As[ac + 0][ar] = v.x; As[ac + 1][ar] = v.y;
            As[ac + 2][ar] = v.z; As[ac + 3][ar] = v.w;
        }
#pragma unroll
        for (int p = 0; p < 2; ++p) {
            int k = (tid >> 5) + p * 8;
            int c4 = (tid & 31) * 4;
            float4 v = *(const float4*)(B + (size_t)(kbase + k) * DIM + c4);
            *(float4*)&Bs[k][c4] = v;
        }
        __syncthreads();
#pragma unroll
        for (int k = 0; k < BK; ++k) {
            float a[TM], b[TN];
            *(float4*)&a[0] = *(const float4*)&As[k][ty * TM];
            *(float4*)&a[4] = *(const float4*)&As[k][ty * TM + 4];
            *(float4*)&b[0] = *(const float4*)&Bs[k][tx * TN];
            *(float4*)&b[4] = *(const float4*)&Bs[k][tx * TN + 4];
#pragma unroll
            for (int i = 0; i < TM; ++i)
#pragma unroll
                for (int j = 0; j < TN; ++j) acc[i][j] += a[i] * b[j];
        }
        __syncthreads();
    }

#pragma unroll
    for (int i = 0; i < TM; ++i) {
        int m = m0 + ty * TM + i;
        if (m >= M) continue;
        float* crow = C + (size_t)m * DIM + tx * TN;
#pragma unroll
        for (int j4 = 0; j4 < TN; j4 += 4) {
            float4 o;
            o.x = acc[i][j4 + 0]; o.y = acc[i][j4 + 1];
            o.z = acc[i][j4 + 2]; o.w = acc[i][j4 + 3];
            *(float4*)(crow + j4) = o;
        }
    }
}

// ------------------------------ GCN scatter (vector RED) -------------------
__global__ void scatter_add_k(const float* __restrict__ feat,
                              const void* __restrict__ edges_raw, long long E,
                              const int* __restrict__ eflag, int Nn,
                              float* __restrict__ out) {
    long long gt = (long long)blockIdx.x * blockDim.x + threadIdx.x;
    long long e = gt >> 5;
    if (e >= E) return;
    int lane = (int)(gt & 31);
    long long s, d;
    if (*eflag) {
        const long long* ed = (const long long*)edges_raw;
        s = ed[e];
        d = ed[E + e];
    } else {
        const int* ed = (const int*)edges_raw;
        s = ed[e];
        d = ed[E + e];
    }
    if (s < 0 || s >= Nn || d < 0 || d >= Nn) return;
    float4 v = *(const float4*)(feat + s * DIM + lane * 4);
    red_add_v4(out + d * DIM + lane * 4, v);
}

// ------------------------------ host launcher ------------------------------
extern "C" void kernel_launch(void* const* d_in, const int* in_sizes, int n_in,
                              void* d_out, int out_size) {
    const float* input_aux = (const float*)d_in[0];
    const void*  edges     = d_in[1];
    const float* W_ih      = (const float*)d_in[2];
    const float* W_hh      = (const float*)d_in[3];
    const float* b_ih      = (const float*)d_in[4];
    const float* b_hh      = (const float*)d_in[5];
    const float* W1        = (const float*)d_in[6];
    const float* b1        = (const float*)d_in[7];
    const float* W2        = (const float*)d_in[8];
    const float* b2        = (const float*)d_in[9];
    float* out = (float*)d_out;

    int Nn  = out_size / DIM;
    int seq = in_sizes[0] / (Nn * DIM);
    long long E = (long long)in_sizes[1] / 2;

    float *h, *c, *t1, *t2, *bsum;
    __half *gates, *xh, *hh, *wc;
    int* eflag;
    cudaGetSymbolAddress((void**)&h,     g_h);
    cudaGetSymbolAddress((void**)&c,     g_c);
    cudaGetSymbolAddress((void**)&gates, g_gates);
    cudaGetSymbolAddress((void**)&t1,    g_t1);
    cudaGetSymbolAddress((void**)&t2,    g_t2);
    cudaGetSymbolAddress((void**)&bsum,  g_bsum);
    cudaGetSymbolAddress((void**)&eflag, g_eflag);
    cudaGetSymbolAddress((void**)&xh,    g_xh);
    cudaGetSymbolAddress((void**)&hh,    g_hh);
    cudaGetSymbolAddress((void**)&wc,    g_wc);

    int nd = Nn * DIM;
    int eb = 256;

    detect_edge_dtype_k<<<1, 256>>>((const int*)edges, 2 * E, eflag);
    bias_sum_k<<<1, NG>>>(b_ih, b_hh, bsum);
    fill_zero_k<<<(nd + eb - 1) / eb, eb>>>(c, nd);
    fill_zero_k<<<(nd / 2 + eb - 1) / eb, eb>>>((float*)hh, nd / 2);

    int xn4 = (seq * nd) / 4;
    cvt_half_k<<<(xn4 + eb - 1) / eb, eb>>>(input_aux, xh, xn4);
    build_wcat_k<<<(NG * 256 + eb - 1) / eb, eb>>>(W_ih, W_hh, wc);

    dim3 ggate((Nn + 127) / 128, 4);
    int cell_threads = Nn * 32;
    for (int t = 0; t < seq; ++t) {
        const __half* xt = xh + (size_t)t * nd;
        gemm_lstm_mma<<<ggate, 256>>>(xt, hh, wc, bsum, gates, Nn);
        lstm_cell_k<<<(cell_threads + eb - 1) / eb, eb>>>(
            gates, c, h, hh, Nn, (t == seq - 1) ? 1 : 0);
    }

    dim3 ggcn((Nn + BM - 1) / BM, 1);
    long long sth = E * 32;
    unsigned sblocks = (unsigned)((sth + eb - 1) / eb);

    gemm_kn_k<<<ggcn, 256>>>(h, W1, t1, Nn);
    fill_zero_k<<<(nd + eb - 1) / eb, eb>>>(t2, nd);
    scatter_add_k<<<sblocks, eb>>>(t1, edges, E, eflag, Nn, t2);
    relu_bias_k<<<(nd + eb - 1) / eb, eb>>>(t2, b1, t1, nd);

    gemm_kn_k<<<ggcn, 256>>>(t1, W2, t2, Nn);
    fill_bias_k<<<(nd + eb - 1) / eb, eb>>>(out, b2, nd);
    scatter_add_k<<<sblocks, eb>>>(t2, edges, E, eflag, Nn, out);
}